// round 8
// baseline (speedup 1.0000x reference)
#include <cuda_runtime.h>
#include <cuda_fp16.h>
#include <cstdint>

#define BATCH 8
#define NN    2048
#define FF    128

// Scratch (device globals — allocation is forbidden)
__device__ float  g_r[BATCH * NN];                       // 64 KB : r = (rowsum(adj)+1)^-1/2
__device__ float  g_Z[BATCH * NN * FF];                  // 8 MB  : Z' = XW, fp32 (self-loop term)
__device__ __half g_Zh[BATCH * FF * NN];                 // 4 MB  : Z' transposed [b][o][j], fp16 (GEMM B)

// ---------------------------------------------------------------------------
// Kernel A: row sums of adj (+1 self loop) -> r = rsqrt(d). Pure read.
// One warp per (b,i) row.
// ---------------------------------------------------------------------------
__global__ void rowsum_kernel(const float* __restrict__ adj) {
    int gwarp = (blockIdx.x * blockDim.x + threadIdx.x) >> 5;
    int lane  = threadIdx.x & 31;
    const float* row = adj + (size_t)gwarp * NN;
    float s = 0.f;
    #pragma unroll
    for (int c = lane * 4; c < NN; c += 32 * 4) {
        float4 v = *(const float4*)(row + c);
        s += (v.x + v.y) + (v.z + v.w);
    }
    #pragma unroll
    for (int o = 16; o; o >>= 1) s += __shfl_xor_sync(0xffffffffu, s, o);
    if (lane == 0) g_r[gwarp] = rsqrtf(s + 1.0f);
}

// ---------------------------------------------------------------------------
// Kernel B: Z' = X @ W (UNSCALED). Writes fp32 [j][o] and fp16 transposed [o][j].
// Does not depend on g_r.
// ---------------------------------------------------------------------------
__global__ void xw_kernel(const float* __restrict__ X, const float* __restrict__ W) {
    const int b  = blockIdx.y;
    const int m0 = blockIdx.x * 64;
    __shared__ float Xs[32][68];
    __shared__ float Ws[32][128];

    const int tid = threadIdx.x;
    const int tx  = tid & 15;
    const int ty  = tid >> 4;

    float acc[4][8];
    #pragma unroll
    for (int m = 0; m < 4; m++)
        #pragma unroll
        for (int n = 0; n < 8; n++) acc[m][n] = 0.f;

    const float* Xb = X + ((size_t)b * NN + m0) * FF;

    for (int k0 = 0; k0 < FF; k0 += 32) {
        #pragma unroll
        for (int t = 0; t < 2; t++) {
            int idx = tid + t * 256;
            int row = idx >> 3, c4 = idx & 7;
            float4 v = *(const float4*)(Xb + (size_t)row * FF + k0 + c4 * 4);
            Xs[c4 * 4 + 0][row] = v.x;
            Xs[c4 * 4 + 1][row] = v.y;
            Xs[c4 * 4 + 2][row] = v.z;
            Xs[c4 * 4 + 3][row] = v.w;
        }
        #pragma unroll
        for (int t = 0; t < 4; t++) {
            int idx = tid + t * 256;
            int row = idx >> 5, c4 = idx & 31;
            *(float4*)&Ws[row][c4 * 4] = *(const float4*)(W + (size_t)(k0 + row) * FF + c4 * 4);
        }
        __syncthreads();
        #pragma unroll
        for (int kk = 0; kk < 32; kk++) {
            float4 a  = *(const float4*)&Xs[kk][ty * 4];
            float4 b0 = *(const float4*)&Ws[kk][tx * 4];
            float4 b1 = *(const float4*)&Ws[kk][64 + tx * 4];
            float av[4] = {a.x, a.y, a.z, a.w};
            float bv[8] = {b0.x, b0.y, b0.z, b0.w, b1.x, b1.y, b1.z, b1.w};
            #pragma unroll
            for (int m = 0; m < 4; m++)
                #pragma unroll
                for (int n = 0; n < 8; n++) acc[m][n] += av[m] * bv[n];
        }
        __syncthreads();
    }

    const int j0 = m0 + ty * 4;

    #pragma unroll
    for (int m = 0; m < 4; m++) {
        float* Zrow = g_Z + ((size_t)b * NN + j0 + m) * FF;
        float4 v0 = make_float4(acc[m][0], acc[m][1], acc[m][2], acc[m][3]);
        float4 v1 = make_float4(acc[m][4], acc[m][5], acc[m][6], acc[m][7]);
        *(float4*)(Zrow + tx * 4)      = v0;
        *(float4*)(Zrow + 64 + tx * 4) = v1;
    }
    __half* ZhB = g_Zh + (size_t)b * FF * NN;
    #pragma unroll
    for (int n = 0; n < 8; n++) {
        int o = (n < 4) ? (tx * 4 + n) : (64 + tx * 4 + (n - 4));
        __half2 p0 = __floats2half2_rn(acc[0][n], acc[1][n]);
        __half2 p1 = __floats2half2_rn(acc[2][n], acc[3][n]);
        uint2 u;
        u.x = reinterpret_cast<unsigned&>(p0);
        u.y = reinterpret_cast<unsigned&>(p1);
        *(uint2*)(ZhB + (size_t)o * NN + j0) = u;
    }
}

// ---------------------------------------------------------------------------
// Kernel C: mma.sync GEMM with inline A conversion.
//   out[b,i,o] = leaky( r_i * (adj[i,:]·(r⊙Z') + r_i·Z'_i) + bias )
// A tile loaded as fp32 (LDG), scaled by r_j, converted to fp16, STS'd.
// B tile (Z'h) via cp.async. BM=64, BN=128, BK=32, 3 stages, 1 sync/iter.
// Grid 256 CTAs -> 2 CTAs/SM. 45KB static smem.
// ---------------------------------------------------------------------------
#define BK      32
#define STAGES  3
#define NIT     (NN / BK)              // 64
#define RPAD    40                     // halves per row (80 B) — conflict-free LDSM
#define A_HALF  (64  * RPAD)           // 2560 halves = 5120 B
#define B_HALF  (128 * RPAD)           // 5120 halves = 10240 B
#define STG_HALF (A_HALF + B_HALF)     // 7680 halves = 15360 B

__global__ void __launch_bounds__(256, 2)
gcn_mma_kernel(const float* __restrict__ adj, const float* __restrict__ bias,
               float* __restrict__ out) {
    __shared__ __half smem[STAGES * STG_HALF];   // 46080 B static

    const int b  = blockIdx.y;
    const int i0 = blockIdx.x * 64;

    const int tid  = threadIdx.x;
    const int warp = tid >> 5, lane = tid & 31;
    const int wm   = warp >> 2, wn = warp & 3;   // 2 x 4 warps, warp tile 32x32
    const int g    = lane >> 2, tig = lane & 3;
    const int lm   = lane >> 3;                  // ldmatrix: matrix index 0..3
    const int lr   = lane & 7;                   // ldmatrix: row within matrix

    const float*  adjF = adj  + (size_t)b * NN * NN + (size_t)i0 * NN;
    const __half* ZhB  = g_Zh + (size_t)b * FF * NN;
    const float*  rB   = g_r  + b * NN;

    float acc[2][4][4];
    #pragma unroll
    for (int mt = 0; mt < 2; mt++)
        #pragma unroll
        for (int nt = 0; nt < 4; nt++)
            #pragma unroll
            for (int q = 0; q < 4; q++) acc[mt][nt][q] = 0.f;

    // A loader: fp32 LDG -> *r_j -> fp16 -> STS. 2 float4 per thread.
    #define LOAD_A(s, k0)                                                         \
    {                                                                             \
        __half* sA = smem + (s) * STG_HALF;                                       \
        const int arow = tid >> 3, ac = tid & 7;                                  \
        float4 rr = *(const float4*)(rB + (k0) + ac * 4);                         \
        _Pragma("unroll")                                                         \
        for (int t = 0; t < 2; t++) {                                             \
            int row = arow + t * 32;                                              \
            float4 gv = *(const float4*)(adjF + (size_t)row * NN + (k0) + ac * 4);\
            __half2 h0 = __floats2half2_rn(gv.x * rr.x, gv.y * rr.y);             \
            __half2 h1 = __floats2half2_rn(gv.z * rr.z, gv.w * rr.w);             \
            uint2 u;                                                              \
            u.x = reinterpret_cast<unsigned&>(h0);                                \
            u.y = reinterpret_cast<unsigned&>(h1);                                \
            *(uint2*)(sA + row * RPAD + ac * 4) = u;                              \
        }                                                                         \
    }

    // B loader: cp.async, 2 x 16B per thread.
    #define LOAD_B(s, k0)                                                         \
    {                                                                             \
        __half* sB = smem + (s) * STG_HALF + A_HALF;                              \
        _Pragma("unroll")                                                         \
        for (int t = 0; t < 2; t++) {                                             \
            int idx = tid + t * 256;                                              \
            int row = idx >> 2, c = idx & 3;                                      \
            uint32_t d = (uint32_t)__cvta_generic_to_shared(sB + row * RPAD + c * 8); \
            const void* gp = ZhB + (size_t)row * NN + (k0) + c * 8;               \
            asm volatile("cp.async.cg.shared.global [%0], [%1], 16;\n"            \
                         :: "r"(d), "l"(gp));                                     \
        }                                                                         \
    }

    // prologue: stages 0,1
    LOAD_A(0, 0);  LOAD_B(0, 0);
    asm volatile("cp.async.commit_group;\n");
    LOAD_A(1, BK); LOAD_B(1, BK);
    asm volatile("cp.async.commit_group;\n");

    for (int i = 0; i < NIT; i++) {
        asm volatile("cp.async.wait_group 1;\n");   // B_i arrived
        __syncthreads();                            // A_i STS visible; slot (i+2)%3 drained

        if (i + 2 < NIT) {
            LOAD_A((i + 2) % STAGES, (i + 2) * BK);
            LOAD_B((i + 2) % STAGES, (i + 2) * BK);
        }
        asm volatile("cp.async.commit_group;\n");

        const __half* Asb = smem + (i % STAGES) * STG_HALF;
        const __half* Bsb = Asb + A_HALF;

        #pragma unroll
        for (int ks = 0; ks < 2; ks++) {
            const int kb = ks * 16;
            uint32_t af[2][4];
            #pragma unroll
            for (int mt = 0; mt < 2; mt++) {
                uint32_t addr = (uint32_t)__cvta_generic_to_shared(
                    &Asb[(wm * 32 + mt * 16 + (lm & 1) * 8 + lr) * RPAD + kb + (lm >> 1) * 8]);
                asm volatile("ldmatrix.sync.aligned.m8n8.x4.shared.b16 {%0,%1,%2,%3}, [%4];\n"
                             : "=r"(af[mt][0]), "=r"(af[mt][1]), "=r"(af[mt][2]), "=r"(af[mt][3])
                             : "r"(addr));
            }
            uint32_t bf[4][2];
            #pragma unroll
            for (int np = 0; np < 2; np++) {
                uint32_t addr = (uint32_t)__cvta_generic_to_shared(
                    &Bsb[(wn * 32 + (np * 2 + (lm >> 1)) * 8 + lr) * RPAD + kb + (lm & 1) * 8]);
                uint32_t t0, t1, t2, t3;
                asm volatile("ldmatrix.sync.aligned.m8n8.x4.shared.b16 {%0,%1,%2,%3}, [%4];\n"
                             : "=r"(t0), "=r"(t1), "=r"(t2), "=r"(t3) : "r"(addr));
                bf[np * 2][0]     = t0; bf[np * 2][1]     = t1;
                bf[np * 2 + 1][0] = t2; bf[np * 2 + 1][1] = t3;
            }
            #pragma unroll
            for (int mt = 0; mt < 2; mt++)
                #pragma unroll
                for (int nt = 0; nt < 4; nt++)
                    asm volatile("mma.sync.aligned.m16n8k16.row.col.f32.f16.f16.f32 "
                                 "{%0,%1,%2,%3}, {%4,%5,%6,%7}, {%8,%9}, {%0,%1,%2,%3};\n"
                                 : "+f"(acc[mt][nt][0]), "+f"(acc[mt][nt][1]),
                                   "+f"(acc[mt][nt][2]), "+f"(acc[mt][nt][3])
                                 : "r"(af[mt][0]), "r"(af[mt][1]), "r"(af[mt][2]), "r"(af[mt][3]),
                                   "r"(bf[nt][0]), "r"(bf[nt][1]));
        }
    }

    // epilogue: + r_i*Z'_i (self loop), * r_i, + bias, leaky relu
    const float* Zb = g_Z + (size_t)b * NN * FF;
    #pragma unroll
    for (int mt = 0; mt < 2; mt++) {
        #pragma unroll
        for (int h = 0; h < 2; h++) {
            const int i = i0 + wm * 32 + mt * 16 + g + h * 8;
            const float ri = rB[i];
            const float* Zrow = Zb + (size_t)i * FF;
            float* orow = out + ((size_t)b * NN + i) * FF;
            #pragma unroll
            for (int nt = 0; nt < 4; nt++) {
                const int o = wn * 32 + nt * 8 + tig * 2;
                float2 z  = *(const float2*)(Zrow + o);
                float2 bb = *(const float2*)(bias + o);
                float v0 = (acc[mt][nt][h * 2 + 0] + ri * z.x) * ri + bb.x;
                float v1 = (acc[mt][nt][h * 2 + 1] + ri * z.y) * ri + bb.y;
                v0 = v0 > 0.f ? v0 : 0.01f * v0;
                v1 = v1 > 0.f ? v1 : 0.01f * v1;
                *(float2*)(orow + o) = make_float2(v0, v1);
            }
        }
    }
}

// ---------------------------------------------------------------------------
extern "C" void kernel_launch(void* const* d_in, const int* in_sizes, int n_in,
                              void* d_out, int out_size) {
    const float* X    = (const float*)d_in[0];   // [8, 2048, 128]
    const float* adj  = (const float*)d_in[1];   // [8, 2048, 2048]
    const float* W    = (const float*)d_in[2];   // [128, 128]
    const float* bias = (const float*)d_in[3];   // [128]
    float* out = (float*)d_out;                  // [8, 2048, 128]

    rowsum_kernel<<<(BATCH * NN) / 8, 256>>>(adj);
    xw_kernel<<<dim3(NN / 64, BATCH), 256>>>(X, W);
    gcn_mma_kernel<<<dim3(NN / 64, BATCH), 256>>>(adj, bias, out);
}